// round 16
// baseline (speedup 1.0000x reference)
#include <cuda_runtime.h>
#include <cuda_bf16.h>
#include <cstdint>

#define D      512
#define NCOLS  100000
#define BROWS  1000
#define NFILT  50
#define MPAD   1024
#define NPAD   100096        /* 782*128 */
#define NTILES 782
#define BAND   0.15f
#define GQCAP  (1 << 22)
#define SQCAP  8192

// ---------------- scratch ----------------
__device__ __align__(16) unsigned short g_qhi[MPAD * D];
__device__ __align__(16) unsigned short g_qlo[MPAD * D];
__device__ __align__(16) unsigned short g_bhi[(size_t)NPAD * D];   // [n][k] K-major
__device__ __align__(16) unsigned short g_blo[(size_t)NPAD * D];
__device__ float g_T[BROWS];
__device__ int   g_qcount;
__device__ uint32_t g_queue[2 * GQCAP];                            // {key, s2}

// ---------------- helpers (sm_80-class PTX only) ----------------
__device__ __forceinline__ uint32_t smem_u32(const void* p) {
    uint32_t a;
    asm("{ .reg .u64 t; cvta.to.shared.u64 t, %1; cvt.u32.u64 %0, t; }" : "=r"(a) : "l"(p));
    return a;
}
__device__ __forceinline__ void cp16(uint32_t dst, const void* src) {
    asm volatile("cp.async.cg.shared.global [%0], [%1], 16;" :: "r"(dst), "l"(src));
}
__device__ __forceinline__ void ldm4(uint32_t* r, uint32_t a) {
    asm volatile("ldmatrix.sync.aligned.m8n8.x4.shared.b16 {%0,%1,%2,%3}, [%4];"
                 : "=r"(r[0]), "=r"(r[1]), "=r"(r[2]), "=r"(r[3]) : "r"(a));
}
__device__ __forceinline__ void mma4(float* c, const uint32_t* a, uint32_t b0, uint32_t b1) {
    asm volatile("mma.sync.aligned.m16n8k16.row.col.f32.bf16.bf16.f32 "
                 "{%0,%1,%2,%3}, {%4,%5,%6,%7}, {%8,%9}, {%0,%1,%2,%3};"
                 : "+f"(c[0]), "+f"(c[1]), "+f"(c[2]), "+f"(c[3])
                 : "r"(a[0]), "r"(a[1]), "r"(a[2]), "r"(a[3]), "r"(b0), "r"(b1));
}
__device__ __forceinline__ void split4(const float* x, unsigned int* hiw, unsigned int* low) {
    #pragma unroll
    for (int p = 0; p < 2; p++) {
        unsigned int u0 = __float_as_uint(x[2 * p]);
        unsigned int u1 = __float_as_uint(x[2 * p + 1]);
        hiw[p] = __byte_perm(u0, u1, 0x7632);
        float h0 = __uint_as_float(u0 & 0xFFFF0000u);
        float h1 = __uint_as_float(u1 & 0xFFFF0000u);
        __nv_bfloat162 lp = __floats2bfloat162_rn(x[2 * p] - h0, x[2 * p + 1] - h1);
        low[p] = *(unsigned int*)&lp;
    }
}

// ---------------------------------------------------------------------------
// convert q -> hi/lo bf16 (pad rows zero); resets queue counter
// ---------------------------------------------------------------------------
__global__ void conv_q_kernel(const float* __restrict__ q) {
    int gid  = blockIdx.x * 256 + threadIdx.x;
    if (gid == 0) g_qcount = 0;
    int base = gid * 8;
    if (base >= MPAD * D) return;
    int row = base >> 9;
    float x[8];
    if (row < BROWS) {
        float4 f0 = *(const float4*)(q + base);
        float4 f1 = *(const float4*)(q + base + 4);
        x[0]=f0.x; x[1]=f0.y; x[2]=f0.z; x[3]=f0.w;
        x[4]=f1.x; x[5]=f1.y; x[6]=f1.z; x[7]=f1.w;
    } else {
        #pragma unroll
        for (int i = 0; i < 8; i++) x[i] = 0.f;
    }
    unsigned int hiw[4], low[4];
    split4(x, hiw, low);
    split4(x + 4, hiw + 2, low + 2);
    *(uint4*)(g_qhi + base) = make_uint4(hiw[0], hiw[1], hiw[2], hiw[3]);
    *(uint4*)(g_qlo + base) = make_uint4(low[0], low[1], low[2], low[3]);
}

// ---------------------------------------------------------------------------
// transpose + convert rhs[k][n] fp32 -> g_bhi/g_blo[n][k] bf16 (K-major)
// ---------------------------------------------------------------------------
__global__ void __launch_bounds__(256)
conv_rhsT_kernel(const float* __restrict__ rhs) {
    __shared__ float st[128][68];
    int t  = threadIdx.x;
    int nb = blockIdx.x * 128;
    int kb = blockIdx.y * 64;

    int r  = t >> 5;
    int c4 = t & 31;
    int n0 = nb + c4 * 4;
    #pragma unroll
    for (int rr = 0; rr < 8; rr++) {
        int krow = rr * 8 + r;
        float4 v;
        const float* src = rhs + (size_t)(kb + krow) * NCOLS + n0;
        if (n0 + 3 < NCOLS) {
            v = *(const float4*)src;
        } else {
            v.x = (n0 + 0 < NCOLS) ? src[0] : 0.f;
            v.y = (n0 + 1 < NCOLS) ? src[1] : 0.f;
            v.z = (n0 + 2 < NCOLS) ? src[2] : 0.f;
            v.w = (n0 + 3 < NCOLS) ? src[3] : 0.f;
        }
        st[c4 * 4 + 0][krow] = v.x;
        st[c4 * 4 + 1][krow] = v.y;
        st[c4 * 4 + 2][krow] = v.z;
        st[c4 * 4 + 3][krow] = v.w;
    }
    __syncthreads();

    int n    = t >> 1;
    int koff = (t & 1) * 32;
    unsigned int hiw[16], low[16];
    #pragma unroll
    for (int jj = 0; jj < 8; jj++) {
        float x[4];
        *(float4*)x = *(const float4*)&st[n][koff + jj * 4];
        split4(x, hiw + jj * 2, low + jj * 2);
    }
    size_t o = (size_t)(nb + n) * D + kb + koff;
    #pragma unroll
    for (int s = 0; s < 4; s++) {
        *(uint4*)(g_bhi + o + s * 8) = make_uint4(hiw[s*4], hiw[s*4+1], hiw[s*4+2], hiw[s*4+3]);
        *(uint4*)(g_blo + o + s * 8) = make_uint4(low[s*4], low[s*4+1], low[s*4+2], low[s*4+3]);
    }
}

// ---------------------------------------------------------------------------
// prep: target score t[b] (fp32 q x (b_hi+b_lo), contiguous reads) and
// out[b] = 1 - #(unique filtered j with s_j >= t)
// ---------------------------------------------------------------------------
__global__ void __launch_bounds__(128)
prep_kernel(const float* __restrict__ q,
            const int* __restrict__ fidx, const int* __restrict__ tgt,
            float* __restrict__ out) {
    int b = blockIdx.x;
    __shared__ int   list[NFILT + 1];
    __shared__ float sv[NFILT + 1];
    __shared__ float qs[D];
    int tid = threadIdx.x, wid = tid >> 5, lane = tid & 31;
    for (int k = tid; k < D; k += 128) qs[k] = q[b * D + k];
    if (tid < NFILT)  list[tid]   = min(max(fidx[b * NFILT + tid], 0), NCOLS - 1);
    if (tid == NFILT) list[NFILT] = min(max(tgt[b], 0), NCOLS - 1);
    __syncthreads();
    for (int d = wid; d <= NFILT; d += 4) {
        int j = list[d];
        const uint4* bh = (const uint4*)(g_bhi + (size_t)j * D);
        const uint4* bl = (const uint4*)(g_blo + (size_t)j * D);
        float acc = 0.f;
        #pragma unroll
        for (int v = 0; v < 2; v++) {
            uint4 h = bh[lane * 2 + v];
            uint4 l = bl[lane * 2 + v];
            unsigned int hw[4] = { h.x, h.y, h.z, h.w };
            unsigned int lw[4] = { l.x, l.y, l.z, l.w };
            int k0 = lane * 16 + v * 8;
            #pragma unroll
            for (int w = 0; w < 4; w++) {
                __nv_bfloat162 hb = *(__nv_bfloat162*)&hw[w];
                __nv_bfloat162 lb = *(__nv_bfloat162*)&lw[w];
                float b0 = __bfloat162float(hb.x) + __bfloat162float(lb.x);
                float b1 = __bfloat162float(hb.y) + __bfloat162float(lb.y);
                acc = fmaf(qs[k0 + w * 2 + 0], b0, acc);
                acc = fmaf(qs[k0 + w * 2 + 1], b1, acc);
            }
        }
        #pragma unroll
        for (int o = 16; o; o >>= 1) acc += __shfl_xor_sync(0xFFFFFFFFu, acc, o);
        if (lane == 0) sv[d] = acc;
    }
    __syncthreads();
    if (tid == 0) {
        float tv = sv[NFILT];
        g_T[b] = tv;
        float corr = 0.f;
        for (int i = 0; i <= NFILT; i++) {
            bool uniq = true;
            for (int jj = 0; jj < i; jj++)
                if (list[jj] == list[i]) { uniq = false; break; }
            if (uniq && sv[i] >= tv) corr += 1.f;
        }
        out[b] = 1.f - corr;
    }
}

// ---------------------------------------------------------------------------
// main GEMM: 2 passes (hi*hi + hi*lo), s2 = s_exact - q_lo.b_hi (+eps).
// CTA 128m x 128n, 8 warps (4m x 2n), warp 32x64, OCCUPANCY 2 (R12 shape —
// best measured duty). K-chunk 128 -> only 4 chunks: half the barrier/wait
// events of R12. smem rows 256B data + 16B pad = 272B stride (row walk = 4
// banks mod 32 -> conflict-free ldmatrix). 2-stage cp.async (204KB smem).
// Epilogue: s2 >= t+BAND -> count; |s2-t| < BAND -> queue for recheck.
// ---------------------------------------------------------------------------
#define A_BYTES    34816                    /* 128 rows * 272B (per array) */
#define B_OFF      A_BYTES
#define STG_BYTES  (3 * A_BYTES)            /* A_hi | B_hi | B_lo = 104448 */
#define SMEM_TOT   (2 * STG_BYTES)          /* 208896 */
#define NCHUNK     4

__global__ void __launch_bounds__(256, 2)
gemm_mma_kernel(float* __restrict__ out) {
    extern __shared__ char smem[];
    uint32_t sb = smem_u32(smem);
    const int tid = threadIdx.x, lane = tid & 31, wid = tid >> 5;
    const int warpM = wid & 3, warpN = wid >> 2;   // 4m x 2n
    const int mRow0 = blockIdx.x * 128;
    const int nBase = blockIdx.y * 128;

    float c[2][8][4];
    #pragma unroll
    for (int a = 0; a < 2; a++)
        #pragma unroll
        for (int b = 0; b < 8; b++)
            #pragma unroll
            for (int e = 0; e < 4; e++) c[a][b][e] = 0.f;

    auto load_chunk = [&](int ch, int slot) {
        uint32_t base = sb + slot * STG_BYTES;
        int k0 = ch * 128;
        #pragma unroll
        for (int i = 0; i < 8; i++) {                 // A hi: 2048 16B segs
            int idx = tid + i * 256;
            int r = idx >> 4, seg = idx & 15;
            uint32_t dst = base + r * 272 + seg * 16;
            cp16(dst, g_qhi + (size_t)(mRow0 + r) * D + k0 + seg * 8);
        }
        #pragma unroll
        for (int i = 0; i < 8; i++) {                 // B hi/lo: 2048 segs each
            int idx = tid + i * 256;
            int r = idx >> 4, seg = idx & 15;
            uint32_t dst = base + B_OFF + r * 272 + seg * 16;
            size_t go = (size_t)(nBase + r) * D + k0 + seg * 8;
            cp16(dst,           g_bhi + go);
            cp16(dst + A_BYTES, g_blo + go);
        }
        asm volatile("cp.async.commit_group;" ::: "memory");
    };

    load_chunk(0, 0);

    for (int ch = 0; ch < NCHUNK; ch++) {
        asm volatile("cp.async.wait_group 0;" ::: "memory");
        __syncthreads();
        if (ch + 1 < NCHUNK) load_chunk(ch + 1, (ch + 1) & 1);

        uint32_t Ab = sb + (ch & 1) * STG_BYTES;
        uint32_t Bb = Ab + B_OFF;
        #pragma unroll
        for (int k16 = 0; k16 < 8; k16++) {
            uint32_t AH[2][4];
            {
                int ar   = warpM * 32 + (lane & 15);
                int koff = k16 * 32 + (lane >> 4) * 16;
                #pragma unroll
                for (int mt = 0; mt < 2; mt++)
                    ldm4(AH[mt], Ab + (ar + mt * 16) * 272 + koff);
            }
            uint32_t BH[4][4], BL[4][4];
            {
                int brow  = warpN * 64 + ((lane >> 4) & 1) * 8 + (lane & 7);
                uint32_t boff = k16 * 32 + ((lane >> 3) & 1) * 16;
                #pragma unroll
                for (int nb = 0; nb < 4; nb++) {
                    uint32_t addr = Bb + (brow + nb * 16) * 272 + boff;
                    ldm4(BH[nb], addr);
                    ldm4(BL[nb], addr + A_BYTES);
                }
            }
            #pragma unroll
            for (int p = 0; p < 2; p++) {
                const uint32_t (*Bf)[4] = p ? BL : BH;
                #pragma unroll
                for (int mt = 0; mt < 2; mt++) {
                    #pragma unroll
                    for (int nb = 0; nb < 4; nb++) {
                        mma4(c[mt][2 * nb],     AH[mt], Bf[nb][0], Bf[nb][1]);
                        mma4(c[mt][2 * nb + 1], AH[mt], Bf[nb][2], Bf[nb][3]);
                    }
                }
            }
        }
    }

    // ---- epilogue: banded count + queue ----
    __syncthreads();                         // all smem reads done; reuse smem
    uint32_t* sq = (uint32_t*)smem;
    __shared__ int scnt;
    __shared__ int sbase;
    if (tid == 0) scnt = 0;
    __syncthreads();

    #pragma unroll
    for (int mt = 0; mt < 2; mt++) {
        #pragma unroll
        for (int h = 0; h < 2; h++) {
            int row = mRow0 + warpM * 32 + mt * 16 + h * 8 + (lane >> 2);
            if (row < BROWS) {
                float tv  = g_T[row];
                float tUp = tv + BAND, tDn = tv - BAND;
                float cnt = 0.f;
                #pragma unroll
                for (int nt = 0; nt < 8; nt++) {
                    int col = nBase + warpN * 64 + nt * 8 + (lane & 3) * 2;
                    #pragma unroll
                    for (int e = 0; e < 2; e++) {
                        int cc = col + e;
                        if (cc < NCOLS) {
                            float s2 = c[mt][nt][h * 2 + e];
                            if (s2 >= tUp) cnt += 1.f;
                            else if (s2 > tDn) {
                                uint32_t key = ((uint32_t)row << 17) | (uint32_t)cc;
                                int slot = atomicAdd(&scnt, 1);
                                if (slot < SQCAP) {
                                    sq[2 * slot]     = key;
                                    sq[2 * slot + 1] = __float_as_uint(s2);
                                } else {
                                    int g = atomicAdd(&g_qcount, 1);
                                    if (g < GQCAP) {
                                        g_queue[2 * g]     = key;
                                        g_queue[2 * g + 1] = __float_as_uint(s2);
                                    }
                                }
                            }
                        }
                    }
                }
                cnt += __shfl_xor_sync(0xFFFFFFFFu, cnt, 1);
                cnt += __shfl_xor_sync(0xFFFFFFFFu, cnt, 2);
                if ((lane & 3) == 0 && cnt != 0.f) atomicAdd(out + row, cnt);
            } else {
                __shfl_xor_sync(0xFFFFFFFFu, 0.f, 1);
                __shfl_xor_sync(0xFFFFFFFFu, 0.f, 2);
            }
        }
    }
    __syncthreads();
    if (tid == 0) {
        int n = min(scnt, SQCAP);
        sbase = (n > 0) ? atomicAdd(&g_qcount, n) : 0;
    }
    __syncthreads();
    int n = min(scnt, SQCAP);
    for (int i = tid; i < n; i += 256) {
        int g = sbase + i;
        if (g < GQCAP) {
            g_queue[2 * g]     = sq[2 * i];
            g_queue[2 * g + 1] = sq[2 * i + 1];
        }
    }
}

// ---------------------------------------------------------------------------
// recheck: s_refined = s2 + q_lo . b_hi  (half-warp per entry -> 2x MLP)
// ---------------------------------------------------------------------------
__global__ void __launch_bounds__(256)
recheck_kernel(float* __restrict__ out) {
    int gh    = (blockIdx.x * 256 + threadIdx.x) >> 4;   // global half-warp id
    int lane16 = threadIdx.x & 15;
    int total = g_qcount;
    if (total > GQCAP) total = GQCAP;
    int nh = gridDim.x * 16;
    for (int i = gh; i < total; i += nh) {
        uint32_t key = g_queue[2 * i];
        float s2 = __uint_as_float(g_queue[2 * i + 1]);
        int row = (int)(key >> 17), col = (int)(key & 0x1FFFFu);
        const uint4* ql = (const uint4*)(g_qlo + (size_t)row * D) + lane16 * 4;
        const uint4* bh = (const uint4*)(g_bhi + (size_t)col * D) + lane16 * 4;
        float d = 0.f;
        #pragma unroll
        for (int v = 0; v < 4; v++) {
            uint4 a = ql[v];
            uint4 b = bh[v];
            unsigned int aw[4] = { a.x, a.y, a.z, a.w };
            unsigned int bw[4] = { b.x, b.y, b.z, b.w };
            #pragma unroll
            for (int w = 0; w < 4; w++) {
                __nv_bfloat162 qa = *(__nv_bfloat162*)&aw[w];
                __nv_bfloat162 bb = *(__nv_bfloat162*)&bw[w];
                d = fmaf(__bfloat162float(qa.x), __bfloat162float(bb.x), d);
                d = fmaf(__bfloat162float(qa.y), __bfloat162float(bb.y), d);
            }
        }
        #pragma unroll
        for (int o = 8; o; o >>= 1) d += __shfl_xor_sync(0xFFFFFFFFu, d, o);
        if (lane16 == 0 && (s2 + d) >= g_T[row]) atomicAdd(out + row, 1.f);
    }
}

// ---------------------------------------------------------------------------
extern "C" void kernel_launch(void* const* d_in, const int* in_sizes, int n_in,
                              void* d_out, int out_size) {
    const float* q    = nullptr;
    const float* rhs  = nullptr;
    const int*   fidx = nullptr;
    const int*   tgt  = nullptr;
    for (int i = 0; i < n_in; i++) {
        switch (in_sizes[i]) {
            case BROWS * D:     q    = (const float*)d_in[i]; break;
            case D * NCOLS:     rhs  = (const float*)d_in[i]; break;
            case BROWS * NFILT: fidx = (const int*)d_in[i];   break;
            case BROWS:         tgt  = (const int*)d_in[i];   break;
        }
    }
    float* out = (float*)d_out;

    cudaFuncSetAttribute(gemm_mma_kernel,
                         cudaFuncAttributeMaxDynamicSharedMemorySize, SMEM_TOT);

    conv_q_kernel<<<256, 256>>>(q);
    conv_rhsT_kernel<<<dim3(NTILES, D / 64), 256>>>(rhs);
    prep_kernel<<<BROWS, 128>>>(q, fidx, tgt, out);
    gemm_mma_kernel<<<dim3(8, NTILES), 256, SMEM_TOT>>>(out);
    recheck_kernel<<<1184, 256>>>(out);
}

// round 17
// speedup vs baseline: 1.3703x; 1.3703x over previous
#include <cuda_runtime.h>
#include <cuda_bf16.h>
#include <cstdint>

#define D      512
#define NCOLS  100000
#define BROWS  1000
#define NFILT  50
#define MPAD   1024
#define NPAD   100096        /* 782*128 */
#define NTILES 782
#define BAND   0.15f
#define GQCAP  (1 << 22)
#define SQCAP  8192

// ---------------- scratch ----------------
__device__ __align__(16) unsigned short g_qhi[MPAD * D];
__device__ __align__(16) unsigned short g_qlo[MPAD * D];
__device__ __align__(16) unsigned short g_bhi[(size_t)NPAD * D];   // [n][k] K-major
__device__ __align__(16) unsigned short g_blo[(size_t)NPAD * D];
__device__ float g_T[BROWS];
__device__ int   g_qcount;
__device__ uint32_t g_queue[2 * GQCAP];                            // {key, s2}

// ---------------- helpers (sm_80-class PTX only) ----------------
__device__ __forceinline__ uint32_t smem_u32(const void* p) {
    uint32_t a;
    asm("{ .reg .u64 t; cvta.to.shared.u64 t, %1; cvt.u32.u64 %0, t; }" : "=r"(a) : "l"(p));
    return a;
}
__device__ __forceinline__ void cp16(uint32_t dst, const void* src) {
    asm volatile("cp.async.cg.shared.global [%0], [%1], 16;" :: "r"(dst), "l"(src));
}
__device__ __forceinline__ void ldm4(uint32_t* r, uint32_t a) {
    asm volatile("ldmatrix.sync.aligned.m8n8.x4.shared.b16 {%0,%1,%2,%3}, [%4];"
                 : "=r"(r[0]), "=r"(r[1]), "=r"(r[2]), "=r"(r[3]) : "r"(a));
}
__device__ __forceinline__ void mma4(float* c, const uint32_t* a, uint32_t b0, uint32_t b1) {
    asm volatile("mma.sync.aligned.m16n8k16.row.col.f32.bf16.bf16.f32 "
                 "{%0,%1,%2,%3}, {%4,%5,%6,%7}, {%8,%9}, {%0,%1,%2,%3};"
                 : "+f"(c[0]), "+f"(c[1]), "+f"(c[2]), "+f"(c[3])
                 : "r"(a[0]), "r"(a[1]), "r"(a[2]), "r"(a[3]), "r"(b0), "r"(b1));
}
__device__ __forceinline__ void split4(const float* x, unsigned int* hiw, unsigned int* low) {
    #pragma unroll
    for (int p = 0; p < 2; p++) {
        unsigned int u0 = __float_as_uint(x[2 * p]);
        unsigned int u1 = __float_as_uint(x[2 * p + 1]);
        hiw[p] = __byte_perm(u0, u1, 0x7632);
        float h0 = __uint_as_float(u0 & 0xFFFF0000u);
        float h1 = __uint_as_float(u1 & 0xFFFF0000u);
        __nv_bfloat162 lp = __floats2bfloat162_rn(x[2 * p] - h0, x[2 * p + 1] - h1);
        low[p] = *(unsigned int*)&lp;
    }
}

// ---------------------------------------------------------------------------
// convert q -> hi/lo bf16 (pad rows zero); resets queue counter
// ---------------------------------------------------------------------------
__global__ void conv_q_kernel(const float* __restrict__ q) {
    int gid  = blockIdx.x * 256 + threadIdx.x;
    if (gid == 0) g_qcount = 0;
    int base = gid * 8;
    if (base >= MPAD * D) return;
    int row = base >> 9;
    float x[8];
    if (row < BROWS) {
        float4 f0 = *(const float4*)(q + base);
        float4 f1 = *(const float4*)(q + base + 4);
        x[0]=f0.x; x[1]=f0.y; x[2]=f0.z; x[3]=f0.w;
        x[4]=f1.x; x[5]=f1.y; x[6]=f1.z; x[7]=f1.w;
    } else {
        #pragma unroll
        for (int i = 0; i < 8; i++) x[i] = 0.f;
    }
    unsigned int hiw[4], low[4];
    split4(x, hiw, low);
    split4(x + 4, hiw + 2, low + 2);
    *(uint4*)(g_qhi + base) = make_uint4(hiw[0], hiw[1], hiw[2], hiw[3]);
    *(uint4*)(g_qlo + base) = make_uint4(low[0], low[1], low[2], low[3]);
}

// ---------------------------------------------------------------------------
// transpose + convert rhs[k][n] fp32 -> g_bhi/g_blo[n][k] bf16 (K-major)
// smem layout [k][n] (pad 132): read-phase stores are contiguous float4
// (conflict-free); write-phase column reads are 2-way (vs 16-way before).
// ---------------------------------------------------------------------------
__global__ void __launch_bounds__(256)
conv_rhsT_kernel(const float* __restrict__ rhs) {
    __shared__ float st[64][132];            // [k][n]
    int t  = threadIdx.x;
    int nb = blockIdx.x * 128;
    int kb = blockIdx.y * 64;

    int r  = t >> 5;
    int c4 = t & 31;
    int n0 = nb + c4 * 4;
    #pragma unroll
    for (int rr = 0; rr < 8; rr++) {
        int krow = rr * 8 + r;
        float4 v;
        const float* src = rhs + (size_t)(kb + krow) * NCOLS + n0;
        if (n0 + 3 < NCOLS) {
            v = *(const float4*)src;
        } else {
            v.x = (n0 + 0 < NCOLS) ? src[0] : 0.f;
            v.y = (n0 + 1 < NCOLS) ? src[1] : 0.f;
            v.z = (n0 + 2 < NCOLS) ? src[2] : 0.f;
            v.w = (n0 + 3 < NCOLS) ? src[3] : 0.f;
        }
        *(float4*)&st[krow][c4 * 4] = v;     // contiguous -> conflict-free
    }
    __syncthreads();

    int n    = t >> 1;                       // local n row 0..127
    int koff = (t & 1) * 32;
    unsigned int hiw[16], low[16];
    #pragma unroll
    for (int jj = 0; jj < 8; jj++) {
        float x[4];
        #pragma unroll
        for (int w = 0; w < 4; w++) x[w] = st[koff + jj * 4 + w][n];
        split4(x, hiw + jj * 2, low + jj * 2);
    }
    size_t o = (size_t)(nb + n) * D + kb + koff;
    #pragma unroll
    for (int s = 0; s < 4; s++) {
        *(uint4*)(g_bhi + o + s * 8) = make_uint4(hiw[s*4], hiw[s*4+1], hiw[s*4+2], hiw[s*4+3]);
        *(uint4*)(g_blo + o + s * 8) = make_uint4(low[s*4], low[s*4+1], low[s*4+2], low[s*4+3]);
    }
}

// ---------------------------------------------------------------------------
// prep: target score t[b] (fp32 q x (b_hi+b_lo), contiguous reads) and
// out[b] = 1 - #(unique filtered j with s_j >= t)
// ---------------------------------------------------------------------------
__global__ void __launch_bounds__(128)
prep_kernel(const float* __restrict__ q,
            const int* __restrict__ fidx, const int* __restrict__ tgt,
            float* __restrict__ out) {
    int b = blockIdx.x;
    __shared__ int   list[NFILT + 1];
    __shared__ float sv[NFILT + 1];
    __shared__ float qs[D];
    int tid = threadIdx.x, wid = tid >> 5, lane = tid & 31;
    for (int k = tid; k < D; k += 128) qs[k] = q[b * D + k];
    if (tid < NFILT)  list[tid]   = min(max(fidx[b * NFILT + tid], 0), NCOLS - 1);
    if (tid == NFILT) list[NFILT] = min(max(tgt[b], 0), NCOLS - 1);
    __syncthreads();
    for (int d = wid; d <= NFILT; d += 4) {
        int j = list[d];
        const uint4* bh = (const uint4*)(g_bhi + (size_t)j * D);
        const uint4* bl = (const uint4*)(g_blo + (size_t)j * D);
        float acc = 0.f;
        #pragma unroll
        for (int v = 0; v < 2; v++) {
            uint4 h = bh[lane * 2 + v];
            uint4 l = bl[lane * 2 + v];
            unsigned int hw[4] = { h.x, h.y, h.z, h.w };
            unsigned int lw[4] = { l.x, l.y, l.z, l.w };
            int k0 = lane * 16 + v * 8;
            #pragma unroll
            for (int w = 0; w < 4; w++) {
                __nv_bfloat162 hb = *(__nv_bfloat162*)&hw[w];
                __nv_bfloat162 lb = *(__nv_bfloat162*)&lw[w];
                float b0 = __bfloat162float(hb.x) + __bfloat162float(lb.x);
                float b1 = __bfloat162float(hb.y) + __bfloat162float(lb.y);
                acc = fmaf(qs[k0 + w * 2 + 0], b0, acc);
                acc = fmaf(qs[k0 + w * 2 + 1], b1, acc);
            }
        }
        #pragma unroll
        for (int o = 16; o; o >>= 1) acc += __shfl_xor_sync(0xFFFFFFFFu, acc, o);
        if (lane == 0) sv[d] = acc;
    }
    __syncthreads();
    if (tid == 0) {
        float tv = sv[NFILT];
        g_T[b] = tv;
        float corr = 0.f;
        for (int i = 0; i <= NFILT; i++) {
            bool uniq = true;
            for (int jj = 0; jj < i; jj++)
                if (list[jj] == list[i]) { uniq = false; break; }
            if (uniq && sv[i] >= tv) corr += 1.f;
        }
        out[b] = 1.f - corr;
    }
}

// ---------------------------------------------------------------------------
// main GEMM (R14 config — frozen): 2 passes (hi*hi + hi*lo).
// CTA 128m x 128n, 8 warps (4m x 2n), warp 32x64, OCCUPANCY 2, K-chunk 64,
// 2-stage cp.async, one barrier per chunk, 144B smem row stride.
// Epilogue: s2 >= t+BAND -> count; |s2-t| < BAND -> queue for recheck.
// ---------------------------------------------------------------------------
#define A_BYTES    18432                    /* 128 rows * 144B (A hi only) */
#define B_OFF      A_BYTES
#define STG_BYTES  (3 * A_BYTES)            /* A_hi | B_hi | B_lo = 55296 */
#define SMEM_TOT   (2 * STG_BYTES)          /* 110592 */
#define NCHUNK     8

__global__ void __launch_bounds__(256, 2)
gemm_mma_kernel(float* __restrict__ out) {
    extern __shared__ char smem[];
    uint32_t sb = smem_u32(smem);
    const int tid = threadIdx.x, lane = tid & 31, wid = tid >> 5;
    const int warpM = wid & 3, warpN = wid >> 2;   // 4m x 2n
    const int mRow0 = blockIdx.x * 128;
    const int nBase = blockIdx.y * 128;

    float c[2][8][4];
    #pragma unroll
    for (int a = 0; a < 2; a++)
        #pragma unroll
        for (int b = 0; b < 8; b++)
            #pragma unroll
            for (int e = 0; e < 4; e++) c[a][b][e] = 0.f;

    auto load_chunk = [&](int ch, int slot) {
        uint32_t base = sb + slot * STG_BYTES;
        int k0 = ch * 64;
        #pragma unroll
        for (int i = 0; i < 4; i++) {                 // A hi: 1024 16B segs
            int idx = tid + i * 256;
            int r = idx >> 3, seg = idx & 7;
            uint32_t dst = base + r * 144 + seg * 16;
            cp16(dst, g_qhi + (size_t)(mRow0 + r) * D + k0 + seg * 8);
        }
        #pragma unroll
        for (int i = 0; i < 4; i++) {                 // B hi/lo: 1024 segs each
            int idx = tid + i * 256;
            int r = idx >> 3, seg = idx & 7;
            uint32_t dst = base + B_OFF + r * 144 + seg * 16;
            size_t go = (size_t)(nBase + r) * D + k0 + seg * 8;
            cp16(dst,           g_bhi + go);
            cp16(dst + A_BYTES, g_blo + go);
        }
        asm volatile("cp.async.commit_group;" ::: "memory");
    };

    load_chunk(0, 0);

    for (int ch = 0; ch < NCHUNK; ch++) {
        asm volatile("cp.async.wait_group 0;" ::: "memory");
        __syncthreads();
        if (ch + 1 < NCHUNK) load_chunk(ch + 1, (ch + 1) & 1);

        uint32_t Ab = sb + (ch & 1) * STG_BYTES;
        uint32_t Bb = Ab + B_OFF;
        #pragma unroll
        for (int k16 = 0; k16 < 4; k16++) {
            uint32_t AH[2][4];
            {
                int ar   = warpM * 32 + (lane & 15);
                int koff = k16 * 32 + (lane >> 4) * 16;
                #pragma unroll
                for (int mt = 0; mt < 2; mt++)
                    ldm4(AH[mt], Ab + (ar + mt * 16) * 144 + koff);
            }
            uint32_t BH[4][4], BL[4][4];
            {
                int brow  = warpN * 64 + ((lane >> 4) & 1) * 8 + (lane & 7);
                uint32_t boff = k16 * 32 + ((lane >> 3) & 1) * 16;
                #pragma unroll
                for (int nb = 0; nb < 4; nb++) {
                    uint32_t addr = Bb + (brow + nb * 16) * 144 + boff;
                    ldm4(BH[nb], addr);
                    ldm4(BL[nb], addr + A_BYTES);
                }
            }
            #pragma unroll
            for (int p = 0; p < 2; p++) {
                const uint32_t (*Bf)[4] = p ? BL : BH;
                #pragma unroll
                for (int mt = 0; mt < 2; mt++) {
                    #pragma unroll
                    for (int nb = 0; nb < 4; nb++) {
                        mma4(c[mt][2 * nb],     AH[mt], Bf[nb][0], Bf[nb][1]);
                        mma4(c[mt][2 * nb + 1], AH[mt], Bf[nb][2], Bf[nb][3]);
                    }
                }
            }
        }
    }

    // ---- epilogue: banded count + queue ----
    __syncthreads();                         // all smem reads done; reuse smem
    uint32_t* sq = (uint32_t*)smem;
    __shared__ int scnt;
    __shared__ int sbase;
    if (tid == 0) scnt = 0;
    __syncthreads();

    #pragma unroll
    for (int mt = 0; mt < 2; mt++) {
        #pragma unroll
        for (int h = 0; h < 2; h++) {
            int row = mRow0 + warpM * 32 + mt * 16 + h * 8 + (lane >> 2);
            if (row < BROWS) {
                float tv  = g_T[row];
                float tUp = tv + BAND, tDn = tv - BAND;
                float cnt = 0.f;
                #pragma unroll
                for (int nt = 0; nt < 8; nt++) {
                    int col = nBase + warpN * 64 + nt * 8 + (lane & 3) * 2;
                    #pragma unroll
                    for (int e = 0; e < 2; e++) {
                        int cc = col + e;
                        if (cc < NCOLS) {
                            float s2 = c[mt][nt][h * 2 + e];
                            if (s2 >= tUp) cnt += 1.f;
                            else if (s2 > tDn) {
                                uint32_t key = ((uint32_t)row << 17) | (uint32_t)cc;
                                int slot = atomicAdd(&scnt, 1);
                                if (slot < SQCAP) {
                                    sq[2 * slot]     = key;
                                    sq[2 * slot + 1] = __float_as_uint(s2);
                                } else {
                                    int g = atomicAdd(&g_qcount, 1);
                                    if (g < GQCAP) {
                                        g_queue[2 * g]     = key;
                                        g_queue[2 * g + 1] = __float_as_uint(s2);
                                    }
                                }
                            }
                        }
                    }
                }
                cnt += __shfl_xor_sync(0xFFFFFFFFu, cnt, 1);
                cnt += __shfl_xor_sync(0xFFFFFFFFu, cnt, 2);
                if ((lane & 3) == 0 && cnt != 0.f) atomicAdd(out + row, cnt);
            } else {
                __shfl_xor_sync(0xFFFFFFFFu, 0.f, 1);
                __shfl_xor_sync(0xFFFFFFFFu, 0.f, 2);
            }
        }
    }
    __syncthreads();
    if (tid == 0) {
        int n = min(scnt, SQCAP);
        sbase = (n > 0) ? atomicAdd(&g_qcount, n) : 0;
    }
    __syncthreads();
    int n = min(scnt, SQCAP);
    for (int i = tid; i < n; i += 256) {
        int g = sbase + i;
        if (g < GQCAP) {
            g_queue[2 * g]     = sq[2 * i];
            g_queue[2 * g + 1] = sq[2 * i + 1];
        }
    }
}

// ---------------------------------------------------------------------------
// recheck: s_refined = s2 + q_lo . b_hi  (half-warp per entry -> 2x MLP)
// ---------------------------------------------------------------------------
__global__ void __launch_bounds__(256)
recheck_kernel(float* __restrict__ out) {
    int gh    = (blockIdx.x * 256 + threadIdx.x) >> 4;   // global half-warp id
    int lane16 = threadIdx.x & 15;
    int total = g_qcount;
    if (total > GQCAP) total = GQCAP;
    int nh = gridDim.x * 16;
    for (int i = gh; i < total; i += nh) {
        uint32_t key = g_queue[2 * i];
        float s2 = __uint_as_float(g_queue[2 * i + 1]);
        int row = (int)(key >> 17), col = (int)(key & 0x1FFFFu);
        const uint4* ql = (const uint4*)(g_qlo + (size_t)row * D) + lane16 * 4;
        const uint4* bh = (const uint4*)(g_bhi + (size_t)col * D) + lane16 * 4;
        float d = 0.f;
        #pragma unroll
        for (int v = 0; v < 4; v++) {
            uint4 a = ql[v];
            uint4 b = bh[v];
            unsigned int aw[4] = { a.x, a.y, a.z, a.w };
            unsigned int bw[4] = { b.x, b.y, b.z, b.w };
            #pragma unroll
            for (int w = 0; w < 4; w++) {
                __nv_bfloat162 qa = *(__nv_bfloat162*)&aw[w];
                __nv_bfloat162 bb = *(__nv_bfloat162*)&bw[w];
                d = fmaf(__bfloat162float(qa.x), __bfloat162float(bb.x), d);
                d = fmaf(__bfloat162float(qa.y), __bfloat162float(bb.y), d);
            }
        }
        #pragma unroll
        for (int o = 8; o; o >>= 1) d += __shfl_xor_sync(0xFFFFFFFFu, d, o);
        if (lane16 == 0 && (s2 + d) >= g_T[row]) atomicAdd(out + row, 1.f);
    }
}

// ---------------------------------------------------------------------------
extern "C" void kernel_launch(void* const* d_in, const int* in_sizes, int n_in,
                              void* d_out, int out_size) {
    const float* q    = nullptr;
    const float* rhs  = nullptr;
    const int*   fidx = nullptr;
    const int*   tgt  = nullptr;
    for (int i = 0; i < n_in; i++) {
        switch (in_sizes[i]) {
            case BROWS * D:     q    = (const float*)d_in[i]; break;
            case D * NCOLS:     rhs  = (const float*)d_in[i]; break;
            case BROWS * NFILT: fidx = (const int*)d_in[i];   break;
            case BROWS:         tgt  = (const int*)d_in[i];   break;
        }
    }
    float* out = (float*)d_out;

    cudaFuncSetAttribute(gemm_mma_kernel,
                         cudaFuncAttributeMaxDynamicSharedMemorySize, SMEM_TOT);

    conv_q_kernel<<<256, 256>>>(q);
    conv_rhsT_kernel<<<dim3(NTILES, D / 64), 256>>>(rhs);
    prep_kernel<<<BROWS, 128>>>(q, fidx, tgt, out);
    gemm_mma_kernel<<<dim3(8, NTILES), 256, SMEM_TOT>>>(out);
    recheck_kernel<<<1184, 256>>>(out);
}